// round 2
// baseline (speedup 1.0000x reference)
#include <cuda_runtime.h>

#define BN   1024
#define TT   256
#define EMB  10
#define HID  256
#define CLS  10

#define NCTA 128
#define NTHR 256
#define BBLK 128   // batch rows per CTA
#define UBLK 16    // hidden units per CTA
#define CCOLS 64   // gate-columns per CTA (UBLK*4, unit-major: c = u*4 + gate)

// Persistent device state (no allocations allowed)
__device__ float d_Ebuf[TT * EMB * BN];   // [t][e][b] pre-gathered embeddings
__device__ float d_H[2][HID * BN];        // [buf][k][b] (transposed h for coalesced reads)
__device__ unsigned g_bar_count;          // zero-init; self-resetting
__device__ unsigned g_bar_gen;

__device__ __forceinline__ float fsig(float x)  { return 1.0f / (1.0f + __expf(-x)); }
__device__ __forceinline__ float ftanh(float x) { return 2.0f * fsig(2.0f * x) - 1.0f; }

__device__ __forceinline__ void grid_barrier() {
    __syncthreads();
    if (threadIdx.x == 0) {
        __threadfence();                                   // release: h writes visible
        unsigned gen = *(volatile unsigned*)&g_bar_gen;
        unsigned ticket = atomicAdd(&g_bar_count, 1u);
        if (ticket == NCTA - 1) {
            g_bar_count = 0;
            __threadfence();
            atomicAdd(&g_bar_gen, 1u);
        } else {
            while (*(volatile unsigned*)&g_bar_gen == gen) { }
        }
        __threadfence();                                   // acquire
    }
    __syncthreads();
}

// Prologue: gather embeddings for all (t,b), and zero h0 (every launch -> replay-safe).
__global__ void embed_kernel(const int* __restrict__ x, const float* __restrict__ emb) {
    int i = blockIdx.x * blockDim.x + threadIdx.x;  // 0 .. BN*TT-1
    int b = i & (BN - 1);
    int t = i >> 10;
    int tok = x[b * TT + t];
#pragma unroll
    for (int e = 0; e < EMB; e++)
        d_Ebuf[(t * EMB + e) * BN + b] = __ldg(&emb[tok * EMB + e]);
    // BN*TT == HID*BN == 262144: every thread zeroes one h0 element
    d_H[0][i] = 0.0f;
}

__global__ void __launch_bounds__(NTHR, 1) lstm_kernel(
    const float* __restrict__ Wgh, const float* __restrict__ Wih,
    const float* __restrict__ Wfh, const float* __restrict__ Woh,
    const float* __restrict__ Wgx, const float* __restrict__ Wix,
    const float* __restrict__ Wfx, const float* __restrict__ Wox,
    const float* __restrict__ bg,  const float* __restrict__ bi,
    const float* __restrict__ bf,  const float* __restrict__ bo)
{
    extern __shared__ float smem[];
    float* Whs = smem;                      // [256][64]  recurrent weights (resident)
    float* Hs  = Whs + HID * CCOLS;         // [256][128] h tile, [k][b]
    float* Wxs = Hs  + HID * BBLK;          // [10][64]
    float* Es  = Wxs + EMB * CCOLS;         // [10][128]
    float* bs  = Es  + EMB * BBLK;          // [64]

    const int tid  = threadIdx.x;
    const int ublk = blockIdx.x & 15;
    const int bblk = blockIdx.x >> 4;
    const int u0   = ublk * UBLK;
    const int b0   = bblk * BBLK;

    const float* Whp[4] = {Wgh, Wih, Wfh, Woh};
    const float* Wxp[4] = {Wgx, Wix, Wfx, Wox};
    const float* bp4[4] = {bg, bi, bf, bo};

    // One-time: stage weight slices into SMEM (unit-major columns c = u*4+gate)
    for (int idx = tid; idx < HID * CCOLS; idx += NTHR) {
        int k = idx >> 6, c = idx & 63;
        Whs[idx] = Whp[c & 3][k * HID + u0 + (c >> 2)];
    }
    for (int idx = tid; idx < EMB * CCOLS; idx += NTHR) {
        int e = idx >> 6, c = idx & 63;
        Wxs[idx] = Wxp[c & 3][e * HID + u0 + (c >> 2)];
    }
    if (tid < CCOLS) bs[tid] = bp4[tid & 3][u0 + (tid >> 2)];
    __syncthreads();

    const int i  = tid & 15;    // row-group: rows b0 + i*8 .. +7
    const int j  = tid >> 4;    // unit: u0 + j
    const int rb = i * 8;

    float cst[8];
#pragma unroll
    for (int r = 0; r < 8; r++) cst[r] = 0.0f;
    const float bias0 = bs[j * 4 + 0], bias1 = bs[j * 4 + 1];
    const float bias2 = bs[j * 4 + 2], bias3 = bs[j * 4 + 3];

    for (int t = 0; t < TT; t++) {
        const float* Hr = d_H[t & 1];
        float*       Hw = d_H[(t + 1) & 1];

        // Stage this step's embedding slice
        for (int idx = tid; idx < EMB * BBLK; idx += NTHR)
            Es[idx] = d_Ebuf[(t * EMB + (idx >> 7)) * BN + b0 + (idx & 127)];

        // Stage h tile [256][128] (coalesced float4, L2-only to dodge stale L1)
#pragma unroll
        for (int it = 0; it < 32; it++) {
            int idx = tid + it * NTHR;          // 0..8191 float4s
            int k   = idx >> 5;                 // 32 f4 per 128-float row
            int bo  = idx & 31;
            float4 v = __ldcg(&((const float4*)(Hr + k * BN + b0))[bo]);
            ((float4*)(Hs + k * BBLK))[bo] = v;
        }
        __syncthreads();

        float acc0[8], acc1[8], acc2[8], acc3[8];
#pragma unroll
        for (int r = 0; r < 8; r++) { acc0[r] = bias0; acc1[r] = bias1; acc2[r] = bias2; acc3[r] = bias3; }

        // x_t @ Wx  (K = 10)
#pragma unroll
        for (int e = 0; e < EMB; e++) {
            float4 a0 = *(const float4*)(Es + e * BBLK + rb);
            float4 a1 = *(const float4*)(Es + e * BBLK + rb + 4);
            float4 w  = *(const float4*)(Wxs + e * CCOLS + j * 4);
            float ar[8] = {a0.x, a0.y, a0.z, a0.w, a1.x, a1.y, a1.z, a1.w};
#pragma unroll
            for (int r = 0; r < 8; r++) {
                acc0[r] += ar[r] * w.x; acc1[r] += ar[r] * w.y;
                acc2[r] += ar[r] * w.z; acc3[r] += ar[r] * w.w;
            }
        }
        // h @ Wh  (K = 256) — FMA-bound main loop
#pragma unroll 8
        for (int k = 0; k < HID; k++) {
            float4 a0 = *(const float4*)(Hs + k * BBLK + rb);
            float4 a1 = *(const float4*)(Hs + k * BBLK + rb + 4);
            float4 w  = *(const float4*)(Whs + k * CCOLS + j * 4);
            float ar[8] = {a0.x, a0.y, a0.z, a0.w, a1.x, a1.y, a1.z, a1.w};
#pragma unroll
            for (int r = 0; r < 8; r++) {
                acc0[r] += ar[r] * w.x; acc1[r] += ar[r] * w.y;
                acc2[r] += ar[r] * w.z; acc3[r] += ar[r] * w.w;
            }
        }

        // Gates + state update (c stays in registers)
        float hv[8];
#pragma unroll
        for (int r = 0; r < 8; r++) {
            float g  = ftanh(acc0[r]);
            float ig = fsig(acc1[r]);
            float fg = fsig(acc2[r]);
            float og = fsig(acc3[r]);
            float c  = g * ig + cst[r] * fg;
            cst[r]   = c;
            hv[r]    = ftanh(c) * og;
        }
        float* wrow = Hw + (u0 + j) * BN + b0 + rb;
        *(float4*)(wrow)     = make_float4(hv[0], hv[1], hv[2], hv[3]);
        *(float4*)(wrow + 4) = make_float4(hv[4], hv[5], hv[6], hv[7]);

        grid_barrier();
    }
}

// Final projection: out[b][c] = h_final[b] @ Wph + bp
__global__ void proj_kernel(const float* __restrict__ Wph, const float* __restrict__ bpv,
                            float* __restrict__ out) {
    __shared__ float Ws[HID * CLS];
    int tid = threadIdx.x;
    for (int idx = tid; idx < HID * CLS; idx += blockDim.x) Ws[idx] = Wph[idx];
    __syncthreads();
    int b = blockIdx.x * blockDim.x + tid;
    float acc[CLS];
#pragma unroll
    for (int c = 0; c < CLS; c++) acc[c] = bpv[c];
    for (int k = 0; k < HID; k++) {
        float h = d_H[0][k * BN + b];   // final h lives in buffer 0 after 256 steps
#pragma unroll
        for (int c = 0; c < CLS; c++) acc[c] += h * Ws[k * CLS + c];
    }
#pragma unroll
    for (int c = 0; c < CLS; c++) out[b * CLS + c] = acc[c];
}

extern "C" void kernel_launch(void* const* d_in, const int* in_sizes, int n_in,
                              void* d_out, int out_size) {
    const int*   x   = (const int*)d_in[0];
    const float* emb = (const float*)d_in[1];
    const float* Wgx = (const float*)d_in[2];
    const float* Wgh = (const float*)d_in[3];
    const float* bg  = (const float*)d_in[4];
    const float* Wix = (const float*)d_in[5];
    const float* Wih = (const float*)d_in[6];
    const float* bi  = (const float*)d_in[7];
    const float* Wfx = (const float*)d_in[8];
    const float* Wfh = (const float*)d_in[9];
    const float* bf  = (const float*)d_in[10];
    const float* Wox = (const float*)d_in[11];
    const float* Woh = (const float*)d_in[12];
    const float* bo  = (const float*)d_in[13];
    const float* Wph = (const float*)d_in[14];
    const float* bp  = (const float*)d_in[15];
    float* out = (float*)d_out;

    embed_kernel<<<(BN * TT) / 256, 256>>>(x, emb);

    size_t smem_bytes = (size_t)(HID * CCOLS + HID * BBLK + EMB * CCOLS + EMB * BBLK + CCOLS) * sizeof(float);
    cudaFuncSetAttribute(lstm_kernel, cudaFuncAttributeMaxDynamicSharedMemorySize, (int)smem_bytes);
    lstm_kernel<<<NCTA, NTHR, smem_bytes>>>(Wgh, Wih, Wfh, Woh,
                                            Wgx, Wix, Wfx, Wox,
                                            bg, bi, bf, bo);

    proj_kernel<<<BN / 128, 128>>>(Wph, bp, out);
}

// round 4
// speedup vs baseline: 1.2729x; 1.2729x over previous
#include <cuda_runtime.h>
#include <cuda_bf16.h>
#include <cstdint>

#define BN   1024
#define TT   256
#define EMB  10
#define HID  256
#define CLS  10

#define NCTA  128
#define NTHR  128
#define MTILE 128      // batch rows per CTA
#define NTILEC 64      // gate cols per CTA (16 units * 4 gates, unit-major)
#define NGRP  8
#define GRPSZ 16

#define KTOT  272      // 256 recurrent + 16 ext (10 emb + bias-1 + pad)
#define KC    17       // k16 chunks
#define RS    544      // SMEM row stride bytes (272 bf16)

// ---------------- persistent device state ---------------------------------
__device__ __nv_bfloat16 d_Ehi[TT * BN * 16];   // [t][b][16] emb hi (incl bias col)
__device__ __nv_bfloat16 d_Elo[TT * BN * 16];
__device__ __nv_bfloat16 d_Hhi[2][BN * HID];    // [buf][b][k]
__device__ __nv_bfloat16 d_Hlo[2][BN * HID];
__device__ unsigned      g_cnt[NGRP * 32];
__device__ unsigned      g_gen[NGRP * 32];

// ---------------- helpers --------------------------------------------------
__device__ __forceinline__ uint32_t smem_u32(const void* p) {
    uint32_t a;
    asm("{ .reg .u64 t; cvta.to.shared.u64 t, %1; cvt.u32.u64 %0, t; }" : "=r"(a) : "l"(p));
    return a;
}
__device__ __forceinline__ float fsig(float x)  { return __fdividef(1.0f, 1.0f + __expf(-x)); }
__device__ __forceinline__ float ftanh(float x) { return 2.0f * fsig(2.0f * x) - 1.0f; }

__device__ __forceinline__ void ldsm_x4(uint32_t* r, uint32_t addr) {
    asm volatile("ldmatrix.sync.aligned.m8n8.x4.shared.b16 {%0,%1,%2,%3}, [%4];"
                 : "=r"(r[0]), "=r"(r[1]), "=r"(r[2]), "=r"(r[3]) : "r"(addr));
}
__device__ __forceinline__ void ldsm_x2(uint32_t* r, uint32_t addr) {
    asm volatile("ldmatrix.sync.aligned.m8n8.x2.shared.b16 {%0,%1}, [%2];"
                 : "=r"(r[0]), "=r"(r[1]) : "r"(addr));
}
__device__ __forceinline__ void mma16816(float* d, const uint32_t* a, const uint32_t* b) {
    asm volatile("mma.sync.aligned.m16n8k16.row.col.f32.bf16.bf16.f32 "
                 "{%0,%1,%2,%3}, {%4,%5,%6,%7}, {%8,%9}, {%0,%1,%2,%3};"
                 : "+f"(d[0]), "+f"(d[1]), "+f"(d[2]), "+f"(d[3])
                 : "r"(a[0]), "r"(a[1]), "r"(a[2]), "r"(a[3]), "r"(b[0]), "r"(b[1]));
}

// SMEM byte offsets from aligned base
#define SO_AHI 0                       // [128][RS]   69632
#define SO_ALO 69632
#define SO_WHI 139264                  // [64][RS]    34816
#define SO_WLO 174080
#define SO_HBH 208896                  // h bounce hi [128][16] bf16 = 4096
#define SO_HBL 212992
#define SMEM_REQ (217088 + 1024)

// ---------------- prologue: embeddings (split-bf16, bias col), zero h0 -----
__global__ void embed_kernel(const int* __restrict__ x, const float* __restrict__ emb) {
    int i = blockIdx.x * blockDim.x + threadIdx.x;   // 0 .. BN*TT-1
    int b = i & (BN - 1);
    int t = i >> 10;
    int tok = x[b * TT + t];
    __nv_bfloat16 hi16[16], lo16[16];
#pragma unroll
    for (int e = 0; e < 16; e++) {
        float v = (e < EMB) ? __ldg(&emb[tok * EMB + e]) : (e == EMB ? 1.0f : 0.0f);
        __nv_bfloat16 h = __float2bfloat16(v);
        hi16[e] = h;
        lo16[e] = __float2bfloat16(v - __bfloat162float(h));
    }
    size_t off = (size_t)(t * BN + b) * 16;
    ((uint4*)(d_Ehi + off))[0] = ((uint4*)hi16)[0];
    ((uint4*)(d_Ehi + off))[1] = ((uint4*)hi16)[1];
    ((uint4*)(d_Elo + off))[0] = ((uint4*)lo16)[0];
    ((uint4*)(d_Elo + off))[1] = ((uint4*)lo16)[1];
    // i spans BN*TT == BN*HID: zero h0 (buffer 0)
    d_Hhi[0][i] = __float2bfloat16(0.0f);
    d_Hlo[0][i] = __float2bfloat16(0.0f);
}

// ---------------- main persistent LSTM kernel ------------------------------
__global__ void __launch_bounds__(NTHR, 1) lstm_kernel(
    const float* __restrict__ Wgh, const float* __restrict__ Wih,
    const float* __restrict__ Wfh, const float* __restrict__ Woh,
    const float* __restrict__ Wgx, const float* __restrict__ Wix,
    const float* __restrict__ Wfx, const float* __restrict__ Wox,
    const float* __restrict__ bg,  const float* __restrict__ bi,
    const float* __restrict__ bf,  const float* __restrict__ bo)
{
    extern __shared__ char smem_raw[];
    char* base = (char*)(((uintptr_t)smem_raw + 1023) & ~(uintptr_t)1023);
    const uint32_t sb = smem_u32(base);

    const int tid = threadIdx.x;
    const int l   = tid & 31;
    const int w   = tid >> 5;
    const int m0  = w * 32;                 // this warp's batch rows
    const int cb  = blockIdx.x & 15;
    const int grp = blockIdx.x >> 4;
    const int u0  = cb * 16;
    const int b0  = grp * MTILE;

    // ---- one-time: stage W (recurrent + ext rows: Wx, bias, pad) ----------
    {
        const float* Whp[4] = {Wgh, Wih, Wfh, Woh};
        const float* Wxp[4] = {Wgx, Wix, Wfx, Wox};
        const float* bp4[4] = {bg, bi, bf, bo};
        for (int idx = tid; idx < NTILEC * KTOT; idx += NTHR) {
            int n = idx & 63, k = idx >> 6;
            int g = n & 3, u = (n >> 2) + u0;
            float v;
            if (k < 256)        v = Whp[g][k * HID + u];
            else if (k < 266)   v = Wxp[g][(k - 256) * HID + u];
            else if (k == 266)  v = bp4[g][u];
            else                v = 0.0f;
            __nv_bfloat16 h = __float2bfloat16(v);
            __nv_bfloat16 o = __float2bfloat16(v - __bfloat162float(h));
            int off = n * RS + k * 2;
            int sw  = off ^ ((n & 7) << 4);
            *(__nv_bfloat16*)(base + SO_WHI + sw) = h;
            *(__nv_bfloat16*)(base + SO_WLO + sw) = o;
        }
    }
    __syncthreads();

    // ---- precomputed fragment addresses -----------------------------------
    // A (x4): row = m0 + mi*16 + (l&15), col16 = l>>4
    uint32_t aBaseHi[2], aBaseLo[2], aXor[2];
#pragma unroll
    for (int mi = 0; mi < 2; mi++) {
        int r = m0 + mi * 16 + (l & 15);
        aBaseHi[mi] = sb + SO_AHI + r * RS + ((l >> 4) << 4);
        aBaseLo[mi] = sb + SO_ALO + r * RS + ((l >> 4) << 4);
        aXor[mi]    = (r & 7) << 4;
    }
    // B (x2): n = j*8 + (l&7), half = (l>>3)&1
    const int nl = l & 7;
    const uint32_t wXor = nl << 4;
    uint32_t wBaseHi[8], wBaseLo[8];
#pragma unroll
    for (int j = 0; j < 8; j++) {
        wBaseHi[j] = sb + SO_WHI + (j * 8 + nl) * RS + (((l >> 3) & 1) << 4);
        wBaseLo[j] = sb + SO_WLO + (j * 8 + nl) * RS + (((l >> 3) & 1) << 4);
    }

    float cst[32];
#pragma unroll
    for (int q = 0; q < 32; q++) cst[q] = 0.0f;

    for (int t = 0; t < TT; t++) {
        const int rb = t & 1;
        const int wb = (t + 1) & 1;

        // ---- stage A: h hi/lo [128][256] + ext emb [128][16] (swizzled) ---
        {
            const __nv_bfloat16* sHi = d_Hhi[rb] + (size_t)b0 * HID;
            const __nv_bfloat16* sLo = d_Hlo[rb] + (size_t)b0 * HID;
#pragma unroll 4
            for (int it = 0; it < 32; it++) {
                int idx = tid + it * NTHR;           // 4096 granules
                int row = idx >> 5, c16 = idx & 31;
                int off = row * RS + c16 * 16;
                int sw  = off ^ ((row & 7) << 4);
                uint4 v = __ldcg((const uint4*)(sHi + row * HID) + c16);
                *(uint4*)(base + SO_AHI + sw) = v;
                uint4 u = __ldcg((const uint4*)(sLo + row * HID) + c16);
                *(uint4*)(base + SO_ALO + sw) = u;
            }
            // ext region: k bytes 512..543 (c16 = 32,33), row = tid
            size_t eoff = (size_t)(t * BN + b0 + tid) * 16;
            const uint4* eh = (const uint4*)(d_Ehi + eoff);
            const uint4* el = (const uint4*)(d_Elo + eoff);
#pragma unroll
            for (int g2 = 0; g2 < 2; g2++) {
                int off = tid * RS + (32 + g2) * 16;
                int sw  = off ^ ((tid & 7) << 4);
                *(uint4*)(base + SO_AHI + sw) = __ldg(eh + g2);
                *(uint4*)(base + SO_ALO + sw) = __ldg(el + g2);
            }
        }
        __syncthreads();

        // ---- 3-chain split-bf16 GEMM: acc[j*8 + mi*4 + q] ------------------
        float acc[64];
#pragma unroll
        for (int q = 0; q < 64; q++) acc[q] = 0.0f;

        for (int kc = 0; kc < KC; kc++) {
            uint32_t ahi[2][4], alo[2][4], whi[8][2], wlo[8][2];
            const uint32_t kb = kc * 32;
#pragma unroll
            for (int mi = 0; mi < 2; mi++) {
                ldsm_x4(ahi[mi], (aBaseHi[mi] + kb) ^ aXor[mi]);
                ldsm_x4(alo[mi], (aBaseLo[mi] + kb) ^ aXor[mi]);
            }
#pragma unroll
            for (int j = 0; j < 8; j++) {
                ldsm_x2(whi[j], (wBaseHi[j] + kb) ^ wXor);
                ldsm_x2(wlo[j], (wBaseLo[j] + kb) ^ wXor);
            }
#pragma unroll
            for (int j = 0; j < 8; j++) {
#pragma unroll
                for (int mi = 0; mi < 2; mi++) {
                    float* d = acc + j * 8 + mi * 4;
                    mma16816(d, ahi[mi], whi[j]);
                    mma16816(d, ahi[mi], wlo[j]);
                    mma16816(d, alo[mi], whi[j]);
                }
            }
        }

        // ---- gates: even lane holds (zg,zi), odd lane holds (zf,zo)+c ------
        __nv_bfloat16* HbH = (__nv_bfloat16*)(base + SO_HBH);
        __nv_bfloat16* HbL = (__nv_bfloat16*)(base + SO_HBL);
        const int uloc = ((l & 3) >> 1);
#pragma unroll
        for (int j = 0; j < 8; j++) {
#pragma unroll
            for (int mi = 0; mi < 2; mi++) {
#pragma unroll
                for (int r = 0; r < 2; r++) {
                    float z0 = acc[j * 8 + mi * 4 + 2 * r];
                    float z1 = acc[j * 8 + mi * 4 + 2 * r + 1];
                    float a  = ftanh(z0) * fsig(z1);              // valid on even lanes
                    float aa = __shfl_sync(0xffffffffu, a, l & ~1);
                    if (l & 1) {
                        int q = j * 4 + mi * 2 + r;
                        float c = aa + cst[q] * fsig(z0);
                        cst[q] = c;
                        float h = ftanh(c) * fsig(z1);
                        __nv_bfloat16 hh = __float2bfloat16(h);
                        int row = m0 + mi * 16 + (l >> 2) + r * 8;
                        int u   = j * 2 + uloc;
                        HbH[row * 16 + u] = hh;
                        HbL[row * 16 + u] = __float2bfloat16(h - __bfloat162float(hh));
                    }
                }
            }
        }
        __syncthreads();

        // ---- cooperative store of h tile to global -------------------------
        {
            __nv_bfloat16* gH = d_Hhi[wb];
            __nv_bfloat16* gL = d_Hlo[wb];
#pragma unroll
            for (int it = 0; it < 2; it++) {
                int g2  = tid + it * NTHR;            // 256 granules of 16B
                int row = g2 >> 1, half = g2 & 1;
                uint4 vh = *(const uint4*)(base + SO_HBH + row * 32 + half * 16);
                uint4 vl = *(const uint4*)(base + SO_HBL + row * 32 + half * 16);
                size_t doff = (size_t)(b0 + row) * HID + u0 + half * 8;
                __stcg((uint4*)(gH + doff), vh);
                __stcg((uint4*)(gL + doff), vl);
            }
        }

        // ---- group barrier (skip after last step) --------------------------
        if (t < TT - 1) {
            __syncthreads();
            if (tid == 0) {
                __threadfence();
                unsigned* cnt = &g_cnt[grp * 32];
                unsigned* gen = &g_gen[grp * 32];
                unsigned g = *(volatile unsigned*)gen;
                unsigned ticket = atomicAdd(cnt, 1u);
                if (ticket == GRPSZ - 1) {
                    *cnt = 0;
                    __threadfence();
                    atomicAdd(gen, 1u);
                } else {
                    while (*(volatile unsigned*)gen == g) { }
                }
                __threadfence();
            }
            __syncthreads();
        }
    }
}

// ---------------- final projection -----------------------------------------
__global__ void proj_kernel(const float* __restrict__ Wph, const float* __restrict__ bpv,
                            float* __restrict__ out) {
    __shared__ float Ws[HID * CLS];
    int tid = threadIdx.x;
    for (int idx = tid; idx < HID * CLS; idx += blockDim.x) Ws[idx] = Wph[idx];
    __syncthreads();
    int b = blockIdx.x * blockDim.x + tid;
    float acc[CLS];
#pragma unroll
    for (int c = 0; c < CLS; c++) acc[c] = bpv[c];
    const __nv_bfloat16* hi = d_Hhi[0] + (size_t)b * HID;   // TT even -> final in buf 0
    const __nv_bfloat16* lo = d_Hlo[0] + (size_t)b * HID;
    for (int k = 0; k < HID; k++) {
        float h = __bfloat162float(hi[k]) + __bfloat162float(lo[k]);
#pragma unroll
        for (int c = 0; c < CLS; c++) acc[c] += h * Ws[k * CLS + c];
    }
#pragma unroll
    for (int c = 0; c < CLS; c++) out[b * CLS + c] = acc[c];
}

extern "C" void kernel_launch(void* const* d_in, const int* in_sizes, int n_in,
                              void* d_out, int out_size) {
    const int*   x   = (const int*)d_in[0];
    const float* emb = (const float*)d_in[1];
    const float* Wgx = (const float*)d_in[2];
    const float* Wgh = (const float*)d_in[3];
    const float* bg  = (const float*)d_in[4];
    const float* Wix = (const float*)d_in[5];
    const float* Wih = (const float*)d_in[6];
    const float* bi  = (const float*)d_in[7];
    const float* Wfx = (const float*)d_in[8];
    const float* Wfh = (const float*)d_in[9];
    const float* bf  = (const float*)d_in[10];
    const float* Wox = (const float*)d_in[11];
    const float* Woh = (const float*)d_in[12];
    const float* bo  = (const float*)d_in[13];
    const float* Wph = (const float*)d_in[14];
    const float* bp  = (const float*)d_in[15];
    float* out = (float*)d_out;

    embed_kernel<<<(BN * TT) / 256, 256>>>(x, emb);

    cudaFuncSetAttribute(lstm_kernel, cudaFuncAttributeMaxDynamicSharedMemorySize, SMEM_REQ);
    lstm_kernel<<<NCTA, NTHR, SMEM_REQ>>>(Wgh, Wih, Wfh, Woh,
                                          Wgx, Wix, Wfx, Wox,
                                          bg, bi, bf, bo);

    proj_kernel<<<BN / 128, 128>>>(Wph, bp, out);
}

// round 7
// speedup vs baseline: 4.0291x; 3.1653x over previous
#include <cuda_runtime.h>
#include <cuda_fp16.h>
#include <cstdint>

#define BN   1024
#define TT   256
#define EMB  10
#define HID  256
#define CLS  10

#define NCTA  128
#define NTHR  256
#define MTILE 32       // batch rows per CTA
#define NGATE 256      // gate cols per CTA (64 units * 4 gates, unit-major)
#define NGRP  32       // batch groups
#define GRPSZ 4        // CTAs per group (column blocks)

#define KTOT  272      // 256 recurrent + 16 ext (10 emb + bias-1 + pad)
#define KC    17
#define RS    544      // SMEM row stride bytes (272 fp16)

// ---------------- persistent device state ---------------------------------
__device__ __half    d_Ef[TT * BN * 16];    // [t][b][16] fp16 emb (incl bias col)
__device__ __half    d_H[2][BN * HID];      // [buf][b][k] fp16 h
__device__ float     d_Hf[BN * HID];        // final h fp32 for projection
__device__ unsigned  g_cnt[NGRP * 32];
__device__ unsigned  g_gen[NGRP * 32];

// ---------------- helpers --------------------------------------------------
__device__ __forceinline__ uint32_t smem_u32(const void* p) {
    uint32_t a;
    asm("{ .reg .u64 t; cvta.to.shared.u64 t, %1; cvt.u32.u64 %0, t; }" : "=r"(a) : "l"(p));
    return a;
}
__device__ __forceinline__ float fsig(float x)  { return __fdividef(1.0f, 1.0f + __expf(-x)); }
__device__ __forceinline__ float ftanh(float x) { return 2.0f * fsig(2.0f * x) - 1.0f; }

__device__ __forceinline__ void ldsm_x4(uint32_t* r, uint32_t addr) {
    asm volatile("ldmatrix.sync.aligned.m8n8.x4.shared.b16 {%0,%1,%2,%3}, [%4];"
                 : "=r"(r[0]), "=r"(r[1]), "=r"(r[2]), "=r"(r[3]) : "r"(addr));
}
__device__ __forceinline__ void mma16816(float* d, const uint32_t* a, const uint32_t* b) {
    asm volatile("mma.sync.aligned.m16n8k16.row.col.f32.f16.f16.f32 "
                 "{%0,%1,%2,%3}, {%4,%5,%6,%7}, {%8,%9}, {%0,%1,%2,%3};"
                 : "+f"(d[0]), "+f"(d[1]), "+f"(d[2]), "+f"(d[3])
                 : "r"(a[0]), "r"(a[1]), "r"(a[2]), "r"(a[3]), "r"(b[0]), "r"(b[1]));
}

// SMEM byte offsets from aligned base
#define SO_W   0                         // [256 n][RS]  139264
#define SO_A   139264                    // [32 m][RS]    17408
#define SO_HB  156672                    // h bounce [32][64] fp16 = 4096
#define SMEM_REQ (160768 + 2048)

// ---------------- prologue: embeddings (fp16, bias col), zero h0 -----------
__global__ void embed_kernel(const int* __restrict__ x, const float* __restrict__ emb) {
    int i = blockIdx.x * blockDim.x + threadIdx.x;   // 0 .. BN*TT-1
    int b = i & (BN - 1);
    int t = i >> 10;
    int tok = x[b * TT + t];
    __half e16[16];
#pragma unroll
    for (int e = 0; e < 16; e++) {
        float v = (e < EMB) ? __ldg(&emb[tok * EMB + e]) : (e == EMB ? 1.0f : 0.0f);
        e16[e] = __float2half(v);
    }
    size_t off = (size_t)(t * BN + b) * 16;
    ((uint4*)(d_Ef + off))[0] = ((uint4*)e16)[0];
    ((uint4*)(d_Ef + off))[1] = ((uint4*)e16)[1];
    // i spans BN*TT == BN*HID: zero h0 (buffer 0)
    d_H[0][i] = __float2half(0.0f);
}

// ---------------- main persistent LSTM kernel ------------------------------
__global__ void __launch_bounds__(NTHR, 1) lstm_kernel(
    const float* __restrict__ Wgh, const float* __restrict__ Wih,
    const float* __restrict__ Wfh, const float* __restrict__ Woh,
    const float* __restrict__ Wgx, const float* __restrict__ Wix,
    const float* __restrict__ Wfx, const float* __restrict__ Wox,
    const float* __restrict__ bg,  const float* __restrict__ bi,
    const float* __restrict__ bf,  const float* __restrict__ bo)
{
    extern __shared__ char smem_raw[];
    char* base = (char*)(((uintptr_t)smem_raw + 1023) & ~(uintptr_t)1023);
    const uint32_t sb = smem_u32(base);

    const int tid = threadIdx.x;
    const int l   = tid & 31;
    const int w   = tid >> 5;
    const int mh  = w & 1;               // warp's M half (16 rows)
    const int nh  = w >> 1;              // warp's N quarter (64 gate cols)
    const int cb  = blockIdx.x & 3;      // column block: units [cb*64, cb*64+64)
    const int grp = blockIdx.x >> 2;     // batch group: rows [grp*32, ...)
    const int ug0 = cb * 64;
    const int b0  = grp * MTILE;

    // ---- one-time: stage W fp16 (recurrent + ext: Wx, bias, pad) ----------
    {
        const float* Whp[4] = {Wgh, Wih, Wfh, Woh};
        const float* Wxp[4] = {Wgx, Wix, Wfx, Wox};
        const float* bp4[4] = {bg, bi, bf, bo};
        for (int idx = tid; idx < NGATE * KTOT; idx += NTHR) {
            int n = idx & 255, k = idx >> 8;
            int g = n & 3, u = ug0 + (n >> 2);
            float v;
            if (k < 256)       v = Whp[g][k * HID + u];
            else if (k < 266)  v = Wxp[g][(k - 256) * HID + u];
            else if (k == 266) v = bp4[g][u];
            else               v = 0.0f;
            int off = n * RS + k * 2;
            int sw  = off ^ ((n & 7) << 4);
            *(__half*)(base + SO_W + sw) = __float2half(v);
        }
    }
    __syncthreads();

    // ---- fragment addresses ------------------------------------------------
    const int arow = mh * 16 + (l & 15);
    const uint32_t aBase = sb + SO_A + arow * RS + ((l >> 4) << 4);
    const uint32_t aXor  = (arow & 7) << 4;
    uint32_t wBase[4];
#pragma unroll
    for (int jp = 0; jp < 4; jp++) {
        int n = nh * 64 + jp * 16 + ((l >> 4) << 3) + (l & 7);
        wBase[jp] = sb + SO_W + n * RS + (((l >> 3) & 1) << 4);
    }
    const uint32_t wXor = (l & 7) << 4;

    float cst[16];
#pragma unroll
    for (int q = 0; q < 16; q++) cst[q] = 0.0f;

    for (int t = 0; t < TT; t++) {
        const int rb = t & 1;
        const int wb = (t + 1) & 1;

        // ---- stage A: h [32][256] fp16 + ext emb [32][16] (swizzled) -------
        {
            const __half* src = d_H[rb] + (size_t)b0 * HID;
#pragma unroll
            for (int it = 0; it < 4; it++) {
                int idx = tid + it * NTHR;        // 0..1023
                int row = idx >> 5, c16 = idx & 31;
                int off = row * RS + c16 * 16;
                int sw  = off ^ ((row & 7) << 4);
                *(uint4*)(base + SO_A + sw) = __ldcg((const uint4*)(src + row * HID) + c16);
            }
            if (tid < 64) {
                int row = tid >> 1, g2 = tid & 1;
                int off = row * RS + (32 + g2) * 16;
                int sw  = off ^ ((row & 7) << 4);
                *(uint4*)(base + SO_A + sw) =
                    __ldg((const uint4*)(d_Ef + (size_t)(t * BN + b0 + row) * 16) + g2);
            }
        }
        __syncthreads();

        // ---- single-chain fp16 GEMM: acc[j*4 + q], j = 0..7 ----------------
        float acc[32];
#pragma unroll
        for (int q = 0; q < 32; q++) acc[q] = 0.0f;

        for (int kc = 0; kc < KC; kc++) {
            const uint32_t kb = kc * 32;
            uint32_t af[4];
            ldsm_x4(af, (aBase + kb) ^ aXor);
            uint32_t wf[4][4];
#pragma unroll
            for (int jp = 0; jp < 4; jp++)
                ldsm_x4(wf[jp], (wBase[jp] + kb) ^ wXor);
#pragma unroll
            for (int jp = 0; jp < 4; jp++) {
                mma16816(acc + jp * 8,     af, &wf[jp][0]);
                mma16816(acc + jp * 8 + 4, af, &wf[jp][2]);
            }
        }

        // ---- gates: even lane (zg,zi), odd lane (zf,zo)+c-state ------------
        __half* Hb = (__half*)(base + SO_HB);
#pragma unroll
        for (int j = 0; j < 8; j++) {
#pragma unroll
            for (int r = 0; r < 2; r++) {
                float z0 = acc[j * 4 + 2 * r];
                float z1 = acc[j * 4 + 2 * r + 1];
                float a  = ftanh(z0) * fsig(z1);           // valid on even lanes
                float aa = __shfl_sync(0xffffffffu, a, l & ~1);
                if (l & 1) {
                    int q = j * 2 + r;
                    float c = aa + cst[q] * fsig(z0);
                    cst[q] = c;
                    float h = ftanh(c) * fsig(z1);
                    int row = mh * 16 + (l >> 2) + r * 8;     // 0..31
                    int ul  = nh * 16 + j * 2 + ((l & 3) >> 1); // unit 0..63
                    if (t < TT - 1) {
                        Hb[row * 64 + ul] = __float2half(h);
                    } else {
                        d_Hf[(size_t)(b0 + row) * HID + ug0 + ul] = h;
                    }
                }
            }
        }
        if (t == TT - 1) break;
        __syncthreads();

        // ---- cooperative store of h tile to global -------------------------
        {
            int row = tid >> 3, chunk = tid & 7;          // 32 rows x 8 granules
            uint4 v = *(const uint4*)(base + SO_HB + row * 128 + chunk * 16);
            __stcg((uint4*)(d_H[wb] + (size_t)(b0 + row) * HID + ug0 + chunk * 8), v);
        }

        // ---- group barrier (4 CTAs) ---------------------------------------
        __syncthreads();
        if (tid == 0) {
            __threadfence();
            unsigned* cnt = &g_cnt[grp * 32];
            unsigned* gen = &g_gen[grp * 32];
            unsigned g = *(volatile unsigned*)gen;
            unsigned ticket = atomicAdd(cnt, 1u);
            if (ticket == GRPSZ - 1) {
                *cnt = 0;
                __threadfence();
                atomicAdd(gen, 1u);
            } else {
                while (*(volatile unsigned*)gen == g) { }
            }
            __threadfence();
        }
        __syncthreads();
    }
}

// ---------------- final projection -----------------------------------------
__global__ void proj_kernel(const float* __restrict__ Wph, const float* __restrict__ bpv,
                            float* __restrict__ out) {
    __shared__ float Ws[HID * CLS];
    int tid = threadIdx.x;
    for (int idx = tid; idx < HID * CLS; idx += blockDim.x) Ws[idx] = Wph[idx];
    __syncthreads();
    int b = blockIdx.x * blockDim.x + tid;
    float acc[CLS];
#pragma unroll
    for (int c = 0; c < CLS; c++) acc[c] = bpv[c];
    const float* hrow = d_Hf + (size_t)b * HID;
    for (int k = 0; k < HID; k++) {
        float h = hrow[k];
#pragma unroll
        for (int c = 0; c < CLS; c++) acc[c] += h * Ws[k * CLS + c];
    }
#pragma unroll
    for (int c = 0; c < CLS; c++) out[b * CLS + c] = acc[c];
}

extern "C" void kernel_launch(void* const* d_in, const int* in_sizes, int n_in,
                              void* d_out, int out_size) {
    const int*   x   = (const int*)d_in[0];
    const float* emb = (const float*)d_in[1];
    const float* Wgx = (const float*)d_in[2];
    const float* Wgh = (const float*)d_in[3];
    const float* bg  = (const float*)d_in[4];
    const float* Wix = (const float*)d_in[5];
    const float* Wih = (const float*)d_in[6];
    const float* bi  = (const float*)d_in[7];
    const float* Wfx = (const float*)d_in[8];
    const float* Wfh = (const float*)d_in[9];
    const float* bf  = (const float*)d_in[10];
    const float* Wox = (const float*)d_in[11];
    const float* Woh = (const float*)d_in[12];
    const float* bo  = (const float*)d_in[13];
    const float* Wph = (const float*)d_in[14];
    const float* bp  = (const float*)d_in[15];
    float* out = (float*)d_out;

    embed_kernel<<<(BN * TT) / 256, 256>>>(x, emb);

    cudaFuncSetAttribute(lstm_kernel, cudaFuncAttributeMaxDynamicSharedMemorySize, SMEM_REQ);
    lstm_kernel<<<NCTA, NTHR, SMEM_REQ>>>(Wgh, Wih, Wfh, Woh,
                                          Wgx, Wix, Wfx, Wox,
                                          bg, bi, bf, bo);

    proj_kernel<<<BN / 128, 128>>>(Wph, bp, out);
}

// round 9
// speedup vs baseline: 6.5266x; 1.6199x over previous
#include <cuda_runtime.h>
#include <cuda_fp16.h>
#include <cstdint>

#define BN   1024
#define TT   256
#define EMB  10
#define HID  256
#define CLS  10

#define NCTA  128
#define NTHR  256
#define MTILE 32       // batch rows per CTA
#define NGATE 256      // gate cols per CTA (64 units * 4 gates, unit-major)
#define GRPSZ 4        // CTAs per cluster (column blocks of one batch group)

#define KTOT  272      // 256 recurrent + 16 ext (10 emb + bias-1 + pad)
#define KC    17
#define RS    544      // SMEM row stride bytes (272 fp16)

// ---------------- persistent device state ---------------------------------
__device__ __half    d_Ef[TT * BN * 16];    // [t][b][16] fp16 emb (incl bias col)
__device__ float     d_Hf[BN * HID];        // final h fp32 for projection

// ---------------- helpers --------------------------------------------------
__device__ __forceinline__ uint32_t smem_u32(const void* p) {
    uint32_t a;
    asm("{ .reg .u64 t; cvta.to.shared.u64 t, %1; cvt.u32.u64 %0, t; }" : "=r"(a) : "l"(p));
    return a;
}
__device__ __forceinline__ float fsig(float x)   { return __fdividef(1.0f, 1.0f + __expf(-x)); }
__device__ __forceinline__ float ftanha(float x) {
    float y; asm("tanh.approx.f32 %0, %1;" : "=f"(y) : "f"(x)); return y;
}
__device__ __forceinline__ void ldsm_x4(uint32_t* r, uint32_t addr) {
    asm volatile("ldmatrix.sync.aligned.m8n8.x4.shared.b16 {%0,%1,%2,%3}, [%4];"
                 : "=r"(r[0]), "=r"(r[1]), "=r"(r[2]), "=r"(r[3]) : "r"(addr));
}
__device__ __forceinline__ void mma16816(float* d, const uint32_t* a, const uint32_t* b) {
    asm volatile("mma.sync.aligned.m16n8k16.row.col.f32.f16.f16.f32 "
                 "{%0,%1,%2,%3}, {%4,%5,%6,%7}, {%8,%9}, {%0,%1,%2,%3};"
                 : "+f"(d[0]), "+f"(d[1]), "+f"(d[2]), "+f"(d[3])
                 : "r"(a[0]), "r"(a[1]), "r"(a[2]), "r"(a[3]), "r"(b[0]), "r"(b[1]));
}
__device__ __forceinline__ uint32_t mapa_u32(uint32_t addr, uint32_t rank) {
    uint32_t r;
    asm("mapa.shared::cluster.u32 %0, %1, %2;" : "=r"(r) : "r"(addr), "r"(rank));
    return r;
}
__device__ __forceinline__ void st_cluster_u4(uint32_t addr, uint4 v) {
    asm volatile("st.shared::cluster.v4.u32 [%0], {%1,%2,%3,%4};"
                 :: "r"(addr), "r"(v.x), "r"(v.y), "r"(v.z), "r"(v.w) : "memory");
}
#define CLUSTER_SYNC() do { \
    asm volatile("barrier.cluster.arrive.aligned;" ::: "memory"); \
    asm volatile("barrier.cluster.wait.aligned;" ::: "memory"); } while (0)

// SMEM byte offsets from aligned base
#define SO_W   0                         // [256 n][RS]  139264
#define ASZ    17408                     // one A buffer [32 m][RS]
#define SO_A   139264                    // A[2] double-buffered (34816)
#define SO_HB  174080                    // h bounce [32][64] fp16 = 4096
#define SMEM_REQ (178176 + 2048)

// ---------------- prologue: embeddings (fp16, bias col) --------------------
__global__ void embed_kernel(const int* __restrict__ x, const float* __restrict__ emb) {
    int i = blockIdx.x * blockDim.x + threadIdx.x;   // 0 .. BN*TT-1
    int b = i & (BN - 1);
    int t = i >> 10;
    int tok = x[b * TT + t];
    __half e16[16];
#pragma unroll
    for (int e = 0; e < 16; e++) {
        float v = (e < EMB) ? __ldg(&emb[tok * EMB + e]) : (e == EMB ? 1.0f : 0.0f);
        e16[e] = __float2half(v);
    }
    size_t off = (size_t)(t * BN + b) * 16;
    ((uint4*)(d_Ef + off))[0] = ((uint4*)e16)[0];
    ((uint4*)(d_Ef + off))[1] = ((uint4*)e16)[1];
}

// ---------------- main persistent LSTM kernel ------------------------------
__global__ void __launch_bounds__(NTHR, 1) __cluster_dims__(GRPSZ, 1, 1)
lstm_kernel(
    const float* __restrict__ Wgh, const float* __restrict__ Wih,
    const float* __restrict__ Wfh, const float* __restrict__ Woh,
    const float* __restrict__ Wgx, const float* __restrict__ Wix,
    const float* __restrict__ Wfx, const float* __restrict__ Wox,
    const float* __restrict__ bg,  const float* __restrict__ bi,
    const float* __restrict__ bf,  const float* __restrict__ bo)
{
    extern __shared__ char smem_raw[];
    char* base = (char*)(((uintptr_t)smem_raw + 1023) & ~(uintptr_t)1023);
    const uint32_t sb = smem_u32(base);

    const int tid = threadIdx.x;
    const int l   = tid & 31;
    const int w   = tid >> 5;
    const int mh  = w & 1;               // warp's M half (16 rows)
    const int nh  = w >> 1;              // warp's N quarter (64 gate cols)
    const int cb  = blockIdx.x & 3;      // cluster rank == column block
    const int grp = blockIdx.x >> 2;     // batch group
    const int ug0 = cb * 64;
    const int b0  = grp * MTILE;

    // peer SMEM bases (incl. self)
    uint32_t peer[GRPSZ];
#pragma unroll
    for (int r = 0; r < GRPSZ; r++) peer[r] = mapa_u32(sb, (uint32_t)r);

    // ---- one-time: stage W fp16 (recurrent + ext: Wx, bias, pad) ----------
    {
        const float* Whp[4] = {Wgh, Wih, Wfh, Woh};
        const float* Wxp[4] = {Wgx, Wix, Wfx, Wox};
        const float* bp4[4] = {bg, bi, bf, bo};
        for (int idx = tid; idx < NGATE * KTOT; idx += NTHR) {
            int n = idx & 255, k = idx >> 8;
            int g = n & 3, u = ug0 + (n >> 2);
            float v;
            if (k < 256)       v = Whp[g][k * HID + u];
            else if (k < 266)  v = Wxp[g][(k - 256) * HID + u];
            else if (k == 266) v = bp4[g][u];
            else               v = 0.0f;
            int off = n * RS + k * 2;
            int sw  = off ^ ((n & 7) << 4);
            *(__half*)(base + SO_W + sw) = __float2half(v);
        }
    }

    // ---- prologue: A[0] = h0 (zeros) + emb(0) ext --------------------------
    {
        uint4 z = make_uint4(0, 0, 0, 0);
        for (int g2 = tid; g2 < ASZ / 16; g2 += NTHR)
            *(uint4*)(base + SO_A + g2 * 16) = z;
        __syncthreads();
        if (tid < 64) {
            int row = tid >> 1, g2 = tid & 1;
            int off = row * RS + (32 + g2) * 16;
            int sw  = off ^ ((row & 7) << 4);
            *(uint4*)(base + SO_A + sw) =
                __ldg((const uint4*)(d_Ef + (size_t)(b0 + row) * 16) + g2);
        }
    }
    __syncthreads();
    CLUSTER_SYNC();

    // ---- fragment addresses ------------------------------------------------
    const int arow = mh * 16 + (l & 15);
    const uint32_t aBase = sb + SO_A + arow * RS + ((l >> 4) << 4);
    const uint32_t aXor  = (arow & 7) << 4;
    uint32_t wBase[4];
#pragma unroll
    for (int jp = 0; jp < 4; jp++) {
        int n = nh * 64 + jp * 16 + ((l >> 4) << 3) + (l & 7);
        wBase[jp] = sb + SO_W + n * RS + (((l >> 3) & 1) << 4);
    }
    const uint32_t wXor = (l & 7) << 4;

    float cst[16];
#pragma unroll
    for (int q = 0; q < 16; q++) cst[q] = 0.0f;

    for (int t = 0; t < TT; t++) {
        const uint32_t rbo = (uint32_t)(t & 1) * ASZ;
        const uint32_t wbo = (uint32_t)((t + 1) & 1) * ASZ;

        // ---- single-chain fp16 GEMM on A[rb]: acc[j*4+q] -------------------
        float acc[32];
#pragma unroll
        for (int q = 0; q < 32; q++) acc[q] = 0.0f;

        for (int kc = 0; kc < KC; kc++) {
            const uint32_t kb = kc * 32;
            uint32_t af[4];
            ldsm_x4(af, (aBase + rbo + kb) ^ aXor);
            uint32_t wf[4][4];
#pragma unroll
            for (int jp = 0; jp < 4; jp++)
                ldsm_x4(wf[jp], (wBase[jp] + kb) ^ wXor);
#pragma unroll
            for (int jp = 0; jp < 4; jp++) {
                mma16816(acc + jp * 8,     af, &wf[jp][0]);
                mma16816(acc + jp * 8 + 4, af, &wf[jp][2]);
            }
        }

        // ---- gates: even lane (zg,zi), odd lane (zf,zo)+c-state ------------
        __half* Hb = (__half*)(base + SO_HB);
#pragma unroll
        for (int j = 0; j < 8; j++) {
#pragma unroll
            for (int r = 0; r < 2; r++) {
                float z0 = acc[j * 4 + 2 * r];
                float z1 = acc[j * 4 + 2 * r + 1];
                float s1 = fsig(z1);                      // even: sig(i); odd: sig(o)
                float a  = ftanha(z0) * s1;               // valid on even lanes
                float aa = __shfl_sync(0xffffffffu, a, l & ~1);
                if (l & 1) {
                    int q = j * 2 + r;
                    float c = aa + cst[q] * fsig(z0);
                    cst[q] = c;
                    float h = ftanha(c) * s1;
                    int row = mh * 16 + (l >> 2) + r * 8;       // 0..31
                    int ul  = nh * 16 + j * 2 + ((l & 3) >> 1); // unit 0..63
                    if (t < TT - 1) {
                        Hb[row * 64 + ul] = __float2half(h);
                    } else {
                        d_Hf[(size_t)(b0 + row) * HID + ug0 + ul] = h;
                    }
                }
            }
        }
        if (t == TT - 1) break;
        __syncthreads();

        // ---- DSMEM broadcast: my h slice -> all 4 peers' A[wb] -------------
        {
            int row = tid >> 3, chunk = tid & 7;          // 256 granules of 16B
            uint4 v = *(const uint4*)(base + SO_HB + row * 128 + chunk * 16);
            int off = row * RS + cb * 128 + chunk * 16;
            uint32_t dst = (uint32_t)(SO_A) + wbo + (uint32_t)(off ^ ((row & 7) << 4));
#pragma unroll
            for (int r = 0; r < GRPSZ; r++)
                st_cluster_u4(peer[r] + dst, v);
        }
        // ---- emb(t+1) ext into local A[wb] ---------------------------------
        if (tid < 64) {
            int row = tid >> 1, g2 = tid & 1;
            int off = row * RS + (32 + g2) * 16;
            int sw  = off ^ ((row & 7) << 4);
            *(uint4*)(base + SO_A + wbo + sw) =
                __ldg((const uint4*)(d_Ef + (size_t)((t + 1) * BN + b0 + row) * 16) + g2);
        }
        CLUSTER_SYNC();
    }
    CLUSTER_SYNC();   // no CTA exits while peers may still write its SMEM
}

// ---------------- final projection -----------------------------------------
__global__ void proj_kernel(const float* __restrict__ Wph, const float* __restrict__ bpv,
                            float* __restrict__ out) {
    __shared__ float Ws[HID * CLS];
    int tid = threadIdx.x;
    for (int idx = tid; idx < HID * CLS; idx += blockDim.x) Ws[idx] = Wph[idx];
    __syncthreads();
    int b = blockIdx.x * blockDim.x + tid;
    float acc[CLS];
#pragma unroll
    for (int c = 0; c < CLS; c++) acc[c] = bpv[c];
    const float* hrow = d_Hf + (size_t)b * HID;
    for (int k = 0; k < HID; k++) {
        float h = hrow[k];
#pragma unroll
        for (int c = 0; c < CLS; c++) acc[c] += h * Ws[k * CLS + c];
    }
#pragma unroll
    for (int c = 0; c < CLS; c++) out[b * CLS + c] = acc[c];
}

extern "C" void kernel_launch(void* const* d_in, const int* in_sizes, int n_in,
                              void* d_out, int out_size) {
    const int*   x   = (const int*)d_in[0];
    const float* emb = (const float*)d_in[1];
    const float* Wgx = (const float*)d_in[2];
    const float* Wgh = (const float*)d_in[3];
    const float* bg  = (const float*)d_in[4];
    const float* Wix = (const float*)d_in[5];
    const float* Wih = (const float*)d_in[6];
    const float* bi  = (const float*)d_in[7];
    const float* Wfx = (const float*)d_in[8];
    const float* Wfh = (const float*)d_in[9];
    const float* bf  = (const float*)d_in[10];
    const float* Wox = (const float*)d_in[11];
    const float* Woh = (const float*)d_in[12];
    const float* bo  = (const float*)d_in[13];
    const float* Wph = (const float*)d_in[14];
    const float* bp  = (const float*)d_in[15];
    float* out = (float*)d_out;

    embed_kernel<<<(BN * TT) / 256, 256>>>(x, emb);

    cudaFuncSetAttribute(lstm_kernel, cudaFuncAttributeMaxDynamicSharedMemorySize, SMEM_REQ);
    lstm_kernel<<<NCTA, NTHR, SMEM_REQ>>>(Wgh, Wih, Wfh, Woh,
                                          Wgx, Wix, Wfx, Wox,
                                          bg, bi, bf, bo);

    proj_kernel<<<BN / 128, 128>>>(Wph, bp, out);
}

// round 11
// speedup vs baseline: 8.8316x; 1.3532x over previous
#include <cuda_runtime.h>
#include <cuda_fp16.h>
#include <cstdint>

#define BN   1024
#define TT   256
#define EMB  10
#define HID  256
#define CLS  10

#define NCTA  128
#define NTHR  512
#define MTILE 32       // batch rows per CTA
#define NGATE 256      // gate cols per CTA (gate-pair-major: (g,i)[0,128) | (f,o)[128,256))
#define GRPSZ 4        // CTAs per cluster (column blocks of one batch group)

#define KTOT  272      // 256 recurrent + 16 ext (10 emb + bias-1 + pad)
#define KC    17
#define RS    544      // SMEM row stride bytes (272 fp16)

// ---------------- persistent device state ---------------------------------
__device__ __half    d_Ef[TT * BN * 16];    // [t][b][16] fp16 emb (incl bias col)
__device__ float     d_Hf[BN * HID];        // final h fp32 for projection

// ---------------- helpers --------------------------------------------------
__device__ __forceinline__ uint32_t smem_u32(const void* p) {
    uint32_t a;
    asm("{ .reg .u64 t; cvta.to.shared.u64 t, %1; cvt.u32.u64 %0, t; }" : "=r"(a) : "l"(p));
    return a;
}
__device__ __forceinline__ float ftanha(float x) {
    float y; asm("tanh.approx.f32 %0, %1;" : "=f"(y) : "f"(x)); return y;
}
__device__ __forceinline__ float fsigt(float x) {     // sigmoid via tanh.approx
    return fmaf(ftanha(0.5f * x), 0.5f, 0.5f);
}
__device__ __forceinline__ void ldsm_x4(uint32_t* r, uint32_t addr) {
    asm volatile("ldmatrix.sync.aligned.m8n8.x4.shared.b16 {%0,%1,%2,%3}, [%4];"
                 : "=r"(r[0]), "=r"(r[1]), "=r"(r[2]), "=r"(r[3]) : "r"(addr));
}
__device__ __forceinline__ void mma16816(float* d, const uint32_t* a, const uint32_t* b) {
    asm volatile("mma.sync.aligned.m16n8k16.row.col.f32.f16.f16.f32 "
                 "{%0,%1,%2,%3}, {%4,%5,%6,%7}, {%8,%9}, {%0,%1,%2,%3};"
                 : "+f"(d[0]), "+f"(d[1]), "+f"(d[2]), "+f"(d[3])
                 : "r"(a[0]), "r"(a[1]), "r"(a[2]), "r"(a[3]), "r"(b[0]), "r"(b[1]));
}
__device__ __forceinline__ uint32_t mapa_u32(uint32_t addr, uint32_t rank) {
    uint32_t r;
    asm("mapa.shared::cluster.u32 %0, %1, %2;" : "=r"(r) : "r"(addr), "r"(rank));
    return r;
}
__device__ __forceinline__ void st_cluster_u4(uint32_t addr, uint4 v) {
    asm volatile("st.shared::cluster.v4.u32 [%0], {%1,%2,%3,%4};"
                 :: "r"(addr), "r"(v.x), "r"(v.y), "r"(v.z), "r"(v.w) : "memory");
}
#define CLUSTER_SYNC() do { \
    asm volatile("barrier.cluster.arrive.aligned;" ::: "memory"); \
    asm volatile("barrier.cluster.wait.aligned;" ::: "memory"); } while (0)

// SMEM byte offsets from aligned base
#define SO_W   0                         // [256 n][RS]  139264
#define ASZ    17408                     // one A buffer [32 m][RS]
#define SO_A   139264                    // A[2] double-buffered (34816)
#define SO_HB  174080                    // h bounce [32][64] fp16 = 4096
#define SMEM_REQ (178176 + 2048)

// ---------------- prologue: embeddings (fp16, bias col) --------------------
__global__ void embed_kernel(const int* __restrict__ x, const float* __restrict__ emb) {
    int i = blockIdx.x * blockDim.x + threadIdx.x;   // 0 .. BN*TT-1
    int b = i & (BN - 1);
    int t = i >> 10;
    int tok = x[b * TT + t];
    __half e16[16];
#pragma unroll
    for (int e = 0; e < 16; e++) {
        float v = (e < EMB) ? __ldg(&emb[tok * EMB + e]) : (e == EMB ? 1.0f : 0.0f);
        e16[e] = __float2half(v);
    }
    size_t off = (size_t)(t * BN + b) * 16;
    ((uint4*)(d_Ef + off))[0] = ((uint4*)e16)[0];
    ((uint4*)(d_Ef + off))[1] = ((uint4*)e16)[1];
}

// ---------------- main persistent LSTM kernel ------------------------------
__global__ void __launch_bounds__(NTHR, 1) __cluster_dims__(GRPSZ, 1, 1)
lstm_kernel(
    const float* __restrict__ Wgh, const float* __restrict__ Wih,
    const float* __restrict__ Wfh, const float* __restrict__ Woh,
    const float* __restrict__ Wgx, const float* __restrict__ Wix,
    const float* __restrict__ Wfx, const float* __restrict__ Wox,
    const float* __restrict__ bg,  const float* __restrict__ bi,
    const float* __restrict__ bf,  const float* __restrict__ bo)
{
    extern __shared__ char smem_raw[];
    char* base = (char*)(((uintptr_t)smem_raw + 1023) & ~(uintptr_t)1023);
    const uint32_t sb = smem_u32(base);

    const int tid = threadIdx.x;
    const int l   = tid & 31;
    const int w   = tid >> 5;
    const int mh  = w & 1;               // warp's M half (16 rows)
    const int nq  = w >> 1;              // warp's unit-octet (8 units)
    const int cb  = blockIdx.x & 3;      // cluster rank == column block
    const int grp = blockIdx.x >> 2;     // batch group
    const int ug0 = cb * 64;
    const int b0  = grp * MTILE;

    // peer SMEM bases (incl. self)
    uint32_t peer[GRPSZ];
#pragma unroll
    for (int r = 0; r < GRPSZ; r++) peer[r] = mapa_u32(sb, (uint32_t)r);

    // ---- one-time: stage W fp16, gate-pair-major N layout ------------------
    // n in [0,128):  u = n>>1, gate = n&1        (g=0, i=1)
    // n in [128,256): u = (n-128)>>1, gate = 2 + (n&1)   (f=2, o=3)
    {
        const float* Whp[4] = {Wgh, Wih, Wfh, Woh};
        const float* Wxp[4] = {Wgx, Wix, Wfx, Wox};
        const float* bp4[4] = {bg, bi, bf, bo};
        for (int idx = tid; idx < NGATE * KTOT; idx += NTHR) {
            int n = idx & 255, k = idx >> 8;
            int g = ((n >> 7) << 1) | (n & 1);
            int u = ug0 + ((n & 127) >> 1);
            float v;
            if (k < 256)       v = Whp[g][k * HID + u];
            else if (k < 266)  v = Wxp[g][(k - 256) * HID + u];
            else if (k == 266) v = bp4[g][u];
            else               v = 0.0f;
            int off = n * RS + k * 2;
            int sw  = off ^ ((n & 7) << 4);
            *(__half*)(base + SO_W + sw) = __float2half(v);
        }
    }

    // ---- prologue: A[0] = h0 (zeros) + emb(0) ext --------------------------
    {
        uint4 z = make_uint4(0, 0, 0, 0);
        for (int g2 = tid; g2 < ASZ / 16; g2 += NTHR)
            *(uint4*)(base + SO_A + g2 * 16) = z;
        __syncthreads();
        if (tid < 64) {
            int row = tid >> 1, g2 = tid & 1;
            int off = row * RS + (32 + g2) * 16;
            int sw  = off ^ ((row & 7) << 4);
            *(uint4*)(base + SO_A + sw) =
                __ldg((const uint4*)(d_Ef + (size_t)(b0 + row) * 16) + g2);
        }
    }
    __syncthreads();
    CLUSTER_SYNC();

    // ---- fragment addresses ------------------------------------------------
    const int arow = mh * 16 + (l & 15);
    const uint32_t aBase = sb + SO_A + arow * RS + ((l >> 4) << 4);
    const uint32_t aXor  = (arow & 7) << 4;
    uint32_t wBase[2];                    // [0]=(g,i) cols, [1]=(f,o) cols
#pragma unroll
    for (int gp = 0; gp < 2; gp++) {
        int n = gp * 128 + nq * 16 + ((l >> 4) << 3) + (l & 7);
        wBase[gp] = sb + SO_W + n * RS + (((l >> 3) & 1) << 4);
    }
    const uint32_t wXor = (l & 7) << 4;

    float cst[4];
#pragma unroll
    for (int q = 0; q < 4; q++) cst[q] = 0.0f;

    for (int t = 0; t < TT; t++) {
        const uint32_t rbo = (uint32_t)(t & 1) * ASZ;
        const uint32_t wbo = (uint32_t)((t + 1) & 1) * ASZ;

        // ---- fp16 GEMM on A[rb]: acc[0..7]=(g,i), acc[8..15]=(f,o) ---------
        float acc[16];
#pragma unroll
        for (int q = 0; q < 16; q++) acc[q] = 0.0f;

        for (int kc = 0; kc < KC; kc++) {
            const uint32_t kb = kc * 32;
            uint32_t af[4];
            ldsm_x4(af, (aBase + rbo + kb) ^ aXor);
            uint32_t wf[2][4];
#pragma unroll
            for (int gp = 0; gp < 2; gp++)
                ldsm_x4(wf[gp], (wBase[gp] + kb) ^ wXor);
#pragma unroll
            for (int gp = 0; gp < 2; gp++) {
                mma16816(acc + gp * 8,     af, &wf[gp][0]);
                mma16816(acc + gp * 8 + 4, af, &wf[gp][2]);
            }
        }

        // ---- prefetch emb(t+1) ext into A[wb] (local-only region) ----------
        if (t < TT - 1 && tid < 64) {
            int row = tid >> 1, g2 = tid & 1;
            int off = row * RS + (32 + g2) * 16;
            int sw  = off ^ ((row & 7) << 4);
            *(uint4*)(base + SO_A + wbo + sw) =
                __ldg((const uint4*)(d_Ef + (size_t)((t + 1) * BN + b0 + row) * 16) + g2);
        }

        // ---- gates: each thread owns all 4 gates of its units --------------
        // slot: mma pair (units nq*8+(l&3) and nq*8+4+(l&3)); rh: row half
        __half* Hb = (__half*)(base + SO_HB);
#pragma unroll
        for (int slot = 0; slot < 2; slot++) {
#pragma unroll
            for (int rh = 0; rh < 2; rh++) {
                int ai = slot * 4 + rh * 2;
                float zg = acc[ai],     zi = acc[ai + 1];
                float zf = acc[8 + ai], zo = acc[8 + ai + 1];
                int q = slot * 2 + rh;
                float c = ftanha(zg) * fsigt(zi) + cst[q] * fsigt(zf);
                cst[q] = c;
                float h = ftanha(c) * fsigt(zo);
                int row = mh * 16 + (l >> 2) + rh * 8;        // 0..31
                int u   = nq * 8 + slot * 4 + (l & 3);        // 0..63
                if (t < TT - 1) {
                    Hb[row * 64 + u] = __float2half(h);
                } else {
                    d_Hf[(size_t)(b0 + row) * HID + ug0 + u] = h;
                }
            }
        }
        if (t == TT - 1) break;
        __syncthreads();

        // ---- DSMEM broadcast: my h slice -> all 4 peers' A[wb] -------------
        if (tid < 256) {
            int row = tid >> 3, chunk = tid & 7;          // 256 granules of 16B
            uint4 v = *(const uint4*)(base + SO_HB + row * 128 + chunk * 16);
            int off = row * RS + cb * 128 + chunk * 16;
            uint32_t dst = (uint32_t)(SO_A) + wbo + (uint32_t)(off ^ ((row & 7) << 4));
#pragma unroll
            for (int r = 0; r < GRPSZ; r++)
                st_cluster_u4(peer[r] + dst, v);
        }
        CLUSTER_SYNC();
    }
    CLUSTER_SYNC();   // no CTA exits while peers may still write its SMEM
}

// ---------------- final projection -----------------------------------------
__global__ void proj_kernel(const float* __restrict__ Wph, const float* __restrict__ bpv,
                            float* __restrict__ out) {
    __shared__ float Ws[HID * CLS];
    int tid = threadIdx.x;
    for (int idx = tid; idx < HID * CLS; idx += blockDim.x) Ws[idx] = Wph[idx];
    __syncthreads();
    int b = blockIdx.x * blockDim.x + tid;
    float acc[CLS];
#pragma unroll
    for (int c = 0; c < CLS; c++) acc[c] = bpv[c];
    const float* hrow = d_Hf + (size_t)b * HID;
    for (int k = 0; k < HID; k++) {
        float h = hrow[k];
#pragma unroll
        for (int c = 0; c < CLS; c++) acc[c] += h * Ws[k * CLS + c];
    }
#pragma unroll
    for (int c = 0; c < CLS; c++) out[b * CLS + c] = acc[c];
}

extern "C" void kernel_launch(void* const* d_in, const int* in_sizes, int n_in,
                              void* d_out, int out_size) {
    const int*   x   = (const int*)d_in[0];
    const float* emb = (const float*)d_in[1];
    const float* Wgx = (const float*)d_in[2];
    const float* Wgh = (const float*)d_in[3];
    const float* bg  = (const float*)d_in[4];
    const float* Wix = (const float*)d_in[5];
    const float* Wih = (const float*)d_in[6];
    const float* bi  = (const float*)d_in[7];
    const float* Wfx = (const float*)d_in[8];
    const float* Wfh = (const float*)d_in[9];
    const float* bf  = (const float*)d_in[10];
    const float* Wox = (const float*)d_in[11];
    const float* Woh = (const float*)d_in[12];
    const float* bo  = (const float*)d_in[13];
    const float* Wph = (const float*)d_in[14];
    const float* bp  = (const float*)d_in[15];
    float* out = (float*)d_out;

    embed_kernel<<<(BN * TT) / 256, 256>>>(x, emb);

    cudaFuncSetAttribute(lstm_kernel, cudaFuncAttributeMaxDynamicSharedMemorySize, SMEM_REQ);
    lstm_kernel<<<NCTA, NTHR, SMEM_REQ>>>(Wgh, Wih, Wfh, Woh,
                                          Wgx, Wix, Wfx, Wox,
                                          bg, bi, bf, bo);

    proj_kernel<<<BN / 128, 128>>>(Wph, bp, out);
}

// round 12
// speedup vs baseline: 9.2128x; 1.0432x over previous
#include <cuda_runtime.h>
#include <cuda_fp16.h>
#include <cstdint>

#define BN   1024
#define TT   256
#define EMB  10
#define HID  256
#define CLS  10

#define NCTA  128
#define NTHR  512
#define MTILE 32       // batch rows per CTA
#define NGATE 256      // gate cols per CTA (gate-pair-major: (g,i)[0,128) | (f,o)[128,256))
#define GRPSZ 4        // CTAs per cluster (column blocks of one batch group)

#define KTOT  272      // 256 recurrent + 16 ext (10 emb + bias-1 + pad)
#define KC    17
#define RS    544      // SMEM row stride bytes (272 fp16)

// ---------------- persistent device state ---------------------------------
__device__ __half    d_Ef[TT * BN * 16];    // [t][b][16] fp16 emb (incl bias col)
__device__ float     d_Hf[BN * HID];        // final h fp32 for projection

// ---------------- helpers --------------------------------------------------
__device__ __forceinline__ uint32_t smem_u32(const void* p) {
    uint32_t a;
    asm("{ .reg .u64 t; cvta.to.shared.u64 t, %1; cvt.u32.u64 %0, t; }" : "=r"(a) : "l"(p));
    return a;
}
__device__ __forceinline__ float ftanha(float x) {
    float y; asm("tanh.approx.f32 %0, %1;" : "=f"(y) : "f"(x)); return y;
}
__device__ __forceinline__ float fsigt(float x) {     // sigmoid via tanh.approx
    return fmaf(ftanha(0.5f * x), 0.5f, 0.5f);
}
__device__ __forceinline__ void ldsm_x4(uint32_t* r, uint32_t addr) {
    asm volatile("ldmatrix.sync.aligned.m8n8.x4.shared.b16 {%0,%1,%2,%3}, [%4];"
                 : "=r"(r[0]), "=r"(r[1]), "=r"(r[2]), "=r"(r[3]) : "r"(addr));
}
__device__ __forceinline__ void mma16816(float* d, const uint32_t* a, const uint32_t* b) {
    asm volatile("mma.sync.aligned.m16n8k16.row.col.f32.f16.f16.f32 "
                 "{%0,%1,%2,%3}, {%4,%5,%6,%7}, {%8,%9}, {%0,%1,%2,%3};"
                 : "+f"(d[0]), "+f"(d[1]), "+f"(d[2]), "+f"(d[3])
                 : "r"(a[0]), "r"(a[1]), "r"(a[2]), "r"(a[3]), "r"(b[0]), "r"(b[1]));
}
__device__ __forceinline__ uint32_t mapa_u32(uint32_t addr, uint32_t rank) {
    uint32_t r;
    asm("mapa.shared::cluster.u32 %0, %1, %2;" : "=r"(r) : "r"(addr), "r"(rank));
    return r;
}
__device__ __forceinline__ void st_cluster_u4(uint32_t addr, uint4 v) {
    asm volatile("st.shared::cluster.v4.u32 [%0], {%1,%2,%3,%4};"
                 :: "r"(addr), "r"(v.x), "r"(v.y), "r"(v.z), "r"(v.w) : "memory");
}
#define CLUSTER_ARRIVE() asm volatile("barrier.cluster.arrive.aligned;" ::: "memory")
#define CLUSTER_WAIT()   asm volatile("barrier.cluster.wait.aligned;"   ::: "memory")
#define CLUSTER_SYNC() do { CLUSTER_ARRIVE(); CLUSTER_WAIT(); } while (0)

// SMEM byte offsets from aligned base
#define SO_W   0                         // [256 n][RS]  139264
#define ASZ    17408                     // one A buffer [32 m][RS]
#define SO_A   139264                    // A[2] double-buffered (34816)
#define SO_HB  174080                    // h bounce [32][64] fp16 = 4096
#define SMEM_REQ (178176 + 2048)

// ---------------- prologue: embeddings (fp16, bias col) --------------------
__global__ void embed_kernel(const int* __restrict__ x, const float* __restrict__ emb) {
    int i = blockIdx.x * blockDim.x + threadIdx.x;   // 0 .. BN*TT-1
    int b = i & (BN - 1);
    int t = i >> 10;
    int tok = x[b * TT + t];
    __half e16[16];
#pragma unroll
    for (int e = 0; e < 16; e++) {
        float v = (e < EMB) ? __ldg(&emb[tok * EMB + e]) : (e == EMB ? 1.0f : 0.0f);
        e16[e] = __float2half(v);
    }
    size_t off = (size_t)(t * BN + b) * 16;
    ((uint4*)(d_Ef + off))[0] = ((uint4*)e16)[0];
    ((uint4*)(d_Ef + off))[1] = ((uint4*)e16)[1];
}

// ---------------- main persistent LSTM kernel ------------------------------
__global__ void __launch_bounds__(NTHR, 1) __cluster_dims__(GRPSZ, 1, 1)
lstm_kernel(
    const float* __restrict__ Wgh, const float* __restrict__ Wih,
    const float* __restrict__ Wfh, const float* __restrict__ Woh,
    const float* __restrict__ Wgx, const float* __restrict__ Wix,
    const float* __restrict__ Wfx, const float* __restrict__ Wox,
    const float* __restrict__ bg,  const float* __restrict__ bi,
    const float* __restrict__ bf,  const float* __restrict__ bo)
{
    extern __shared__ char smem_raw[];
    char* base = (char*)(((uintptr_t)smem_raw + 1023) & ~(uintptr_t)1023);
    const uint32_t sb = smem_u32(base);

    const int tid = threadIdx.x;
    const int l   = tid & 31;
    const int w   = tid >> 5;
    const int mh  = w & 1;               // warp's M half (16 rows)
    const int nq  = w >> 1;              // warp's unit-octet (8 units)
    const int cb  = blockIdx.x & 3;      // cluster rank == column block
    const int grp = blockIdx.x >> 2;     // batch group
    const int ug0 = cb * 64;
    const int b0  = grp * MTILE;

    // peer SMEM bases (incl. self)
    uint32_t peer[GRPSZ];
#pragma unroll
    for (int r = 0; r < GRPSZ; r++) peer[r] = mapa_u32(sb, (uint32_t)r);

    // ---- one-time: stage W fp16, gate-pair-major N layout ------------------
    {
        const float* Whp[4] = {Wgh, Wih, Wfh, Woh};
        const float* Wxp[4] = {Wgx, Wix, Wfx, Wox};
        const float* bp4[4] = {bg, bi, bf, bo};
        for (int idx = tid; idx < NGATE * KTOT; idx += NTHR) {
            int n = idx & 255, k = idx >> 8;
            int g = ((n >> 7) << 1) | (n & 1);
            int u = ug0 + ((n & 127) >> 1);
            float v;
            if (k < 256)       v = Whp[g][k * HID + u];
            else if (k < 266)  v = Wxp[g][(k - 256) * HID + u];
            else if (k == 266) v = bp4[g][u];
            else               v = 0.0f;
            int off = n * RS + k * 2;
            int sw  = off ^ ((n & 7) << 4);
            *(__half*)(base + SO_W + sw) = __float2half(v);
        }
    }

    // ---- prologue: A[0] = h0 (zeros) + emb(0) ext --------------------------
    {
        uint4 z = make_uint4(0, 0, 0, 0);
        for (int g2 = tid; g2 < ASZ / 16; g2 += NTHR)
            *(uint4*)(base + SO_A + g2 * 16) = z;
        __syncthreads();
        if (tid < 64) {
            int row = tid >> 1, g2 = tid & 1;
            int off = row * RS + (32 + g2) * 16;
            int sw  = off ^ ((row & 7) << 4);
            *(uint4*)(base + SO_A + sw) =
                __ldg((const uint4*)(d_Ef + (size_t)(b0 + row) * 16) + g2);
        }
    }
    __syncthreads();
    CLUSTER_SYNC();

    // ---- fragment addresses ------------------------------------------------
    const int arow = mh * 16 + (l & 15);
    const uint32_t aBase = sb + SO_A + arow * RS + ((l >> 4) << 4);
    const uint32_t aXor  = (arow & 7) << 4;
    uint32_t wBase[2];                    // [0]=(g,i) cols, [1]=(f,o) cols
#pragma unroll
    for (int gp = 0; gp < 2; gp++) {
        int n = gp * 128 + nq * 16 + ((l >> 4) << 3) + (l & 7);
        wBase[gp] = sb + SO_W + n * RS + (((l >> 3) & 1) << 4);
    }
    const uint32_t wXor = (l & 7) << 4;

    float cst[4];
#pragma unroll
    for (int q = 0; q < 4; q++) cst[q] = 0.0f;

#define DO_KC(kcv) do {                                                       \
        const uint32_t kb = (uint32_t)(kcv) * 32;                             \
        uint32_t af[4];                                                       \
        ldsm_x4(af, (aBase + rbo + kb) ^ aXor);                               \
        uint32_t wf0[4], wf1[4];                                              \
        ldsm_x4(wf0, (wBase[0] + kb) ^ wXor);                                 \
        ldsm_x4(wf1, (wBase[1] + kb) ^ wXor);                                 \
        mma16816(acc,      af, &wf0[0]);                                      \
        mma16816(acc + 4,  af, &wf0[2]);                                      \
        mma16816(acc + 8,  af, &wf1[0]);                                      \
        mma16816(acc + 12, af, &wf1[2]);                                      \
    } while (0)

    for (int t = 0; t < TT; t++) {
        const uint32_t rbo = (uint32_t)(t & 1) * ASZ;
        const uint32_t wbo = (uint32_t)((t + 1) & 1) * ASZ;

        float acc[16];
#pragma unroll
        for (int q = 0; q < 16; q++) acc[q] = 0.0f;

        // [A] part1: locally-produced kcs (own column region + ext) ----------
        {
            const int cbk = cb * 4;
#pragma unroll
            for (int i = 0; i < 4; i++) DO_KC(cbk + i);
            DO_KC(16);
        }

        // [B] wait for peers' h(t) slices (arrivals from step t-1) -----------
        if (t > 0) CLUSTER_WAIT();

        // [C] part2: peer kcs, nearest-producer order ------------------------
#pragma unroll
        for (int rr = 1; rr < 4; rr++) {
            const int r4 = (((cb + rr) & 3) << 2);
#pragma unroll
            for (int i = 0; i < 4; i++) DO_KC(r4 + i);
        }

        // [D] prefetch emb(t+1) ext into A[wb] (local-only region) -----------
        if (t < TT - 1 && tid < 64) {
            int row = tid >> 1, g2 = tid & 1;
            int off = row * RS + (32 + g2) * 16;
            int sw  = off ^ ((row & 7) << 4);
            *(uint4*)(base + SO_A + wbo + sw) =
                __ldg((const uint4*)(d_Ef + (size_t)((t + 1) * BN + b0 + row) * 16) + g2);
        }

        // [D] gates: each thread owns all 4 gates of its units ---------------
        __half* Hb = (__half*)(base + SO_HB);
#pragma unroll
        for (int slot = 0; slot < 2; slot++) {
#pragma unroll
            for (int rh = 0; rh < 2; rh++) {
                int ai = slot * 4 + rh * 2;
                float zg = acc[ai],     zi = acc[ai + 1];
                float zf = acc[8 + ai], zo = acc[8 + ai + 1];
                int q = slot * 2 + rh;
                float c = ftanha(zg) * fsigt(zi) + cst[q] * fsigt(zf);
                cst[q] = c;
                float h = ftanha(c) * fsigt(zo);
                int row = mh * 16 + (l >> 2) + rh * 8;        // 0..31
                int u   = nq * 8 + slot * 4 + (l & 3);        // 0..63
                if (t < TT - 1) {
                    Hb[row * 64 + u] = __float2half(h);
                } else {
                    d_Hf[(size_t)(b0 + row) * HID + ug0 + u] = h;
                }
            }
        }
        if (t == TT - 1) break;

        // [E] broadcast my h slice -> all 4 peers' A[wb] ---------------------
        __syncthreads();
        if (tid < 256) {
            int row = tid >> 3, chunk = tid & 7;          // 256 granules of 16B
            uint4 v = *(const uint4*)(base + SO_HB + row * 128 + chunk * 16);
            int off = row * RS + cb * 128 + chunk * 16;
            uint32_t dst = (uint32_t)(SO_A) + wbo + (uint32_t)(off ^ ((row & 7) << 4));
#pragma unroll
            for (int r = 0; r < GRPSZ; r++)
                st_cluster_u4(peer[r] + dst, v);
        }

        // [F] signal my slice stored; order own-region stores for next [A] ---
        CLUSTER_ARRIVE();
        __syncthreads();
    }
    CLUSTER_SYNC();   // no CTA exits while peers may still write its SMEM
#undef DO_KC
}

// ---------------- final projection -----------------------------------------
__global__ void proj_kernel(const float* __restrict__ Wph, const float* __restrict__ bpv,
                            float* __restrict__ out) {
    __shared__ float Ws[HID * CLS];
    int tid = threadIdx.x;
    for (int idx = tid; idx < HID * CLS; idx += blockDim.x) Ws[idx] = Wph[idx];
    __syncthreads();
    int b = blockIdx.x * blockDim.x + tid;
    float acc[CLS];
#pragma unroll
    for (int c = 0; c < CLS; c++) acc[c] = bpv[c];
    const float* hrow = d_Hf + (size_t)b * HID;
    for (int k = 0; k < HID; k++) {
        float h = hrow[k];
#pragma unroll
        for (int c = 0; c < CLS; c++) acc[c] += h * Ws[k * CLS + c];
    }
#pragma unroll
    for (int c = 0; c < CLS; c++) out[b * CLS + c] = acc[c];
}

extern "C" void kernel_launch(void* const* d_in, const int* in_sizes, int n_in,
                              void* d_out, int out_size) {
    const int*   x   = (const int*)d_in[0];
    const float* emb = (const float*)d_in[1];
    const float* Wgx = (const float*)d_in[2];
    const float* Wgh = (const float*)d_in[3];
    const float* bg  = (const float*)d_in[4];
    const float* Wix = (const float*)d_in[5];
    const float* Wih = (const float*)d_in[6];
    const float* bi  = (const float*)d_in[7];
    const float* Wfx = (const float*)d_in[8];
    const float* Wfh = (const float*)d_in[9];
    const float* bf  = (const float*)d_in[10];
    const float* Wox = (const float*)d_in[11];
    const float* Woh = (const float*)d_in[12];
    const float* bo  = (const float*)d_in[13];
    const float* Wph = (const float*)d_in[14];
    const float* bp  = (const float*)d_in[15];
    float* out = (float*)d_out;

    embed_kernel<<<(BN * TT) / 256, 256>>>(x, emb);

    cudaFuncSetAttribute(lstm_kernel, cudaFuncAttributeMaxDynamicSharedMemorySize, SMEM_REQ);
    lstm_kernel<<<NCTA, NTHR, SMEM_REQ>>>(Wgh, Wih, Wfh, Woh,
                                          Wgx, Wix, Wfx, Wox,
                                          bg, bi, bf, bo);

    proj_kernel<<<BN / 128, 128>>>(Wph, bp, out);
}